// round 10
// baseline (speedup 1.0000x reference)
#include <cuda_runtime.h>
#include <cstdint>

#define B 32
#define NN 20000
#define F 64
#define JO 64
#define E 16
#define NCHUNK 100
#define CHUNK 200
#define NPB3 100

// Scratch (static device arrays — no allocation)
__device__ float g_zpart[B * NCHUNK * F * E];   // [b][chunk][i*16+f]  13.1 MB
__device__ float g_z[B * F * E];                // [b][i][f]
__device__ float g_w[B * JO * E];               // [b][j][e]

typedef unsigned long long u64;

static __device__ __forceinline__ u64 ffma2(u64 a, u64 b, u64 c) {
    u64 d;
    asm("fma.rn.f32x2 %0, %1, %2, %3;" : "=l"(d) : "l"(a), "l"(b), "l"(c));
    return d;
}
static __device__ __forceinline__ u64 pack2(float lo, float hi) {
    u64 r; asm("mov.b64 %0, {%1, %2};" : "=l"(r) : "f"(lo), "f"(hi)); return r;
}
static __device__ __forceinline__ float2 unpack2(u64 v) {
    float2 f; asm("mov.b64 {%0, %1}, %2;" : "=f"(f.x), "=f"(f.y) : "l"(v)); return f;
}

// ---------------------------------------------------------------------------
// Kernel 1: partial z[b,i,f] = sum_m V[m,f] * x[b,m,i] over one 200-row chunk.
// grid (100, 32) = 3200 blocks, 256 threads, occ 3 (24 warps/SM).
// LSU fix: f-split of 2 only -> x LDG dup 2-way (1 LDG.128/warp-row,
// ~4.3k warp-LDG/SM ~ 9.6us issue vs 38us before); V staged in smem once per
// block (coalesced), then broadcast LDS (cheap, separate pipe).
// Lane: ig = lane>>1 (i quad), fh = lane&1 (f half). Warp covers 1 row.
// Batch 5 rows -> 5*256B*24w = 30KB/SM in flight (Little's law ~26KB).
// Thread acc: 4i x 4 f-pairs = 16 u64 (32 regs).
// ---------------------------------------------------------------------------
__global__ void __launch_bounds__(256, 3)
k1_project(const float* __restrict__ x, const float* __restrict__ V) {
    const int c    = blockIdx.x;
    const int b    = blockIdx.y;
    const int t    = threadIdx.x;
    const int w    = t >> 5;
    const int lane = t & 31;
    const int ig   = lane >> 1;
    const int fh   = lane & 1;

    __shared__ float smem_u[8 * 64 * 18];     // 36.9 KB: sV (first 3200) then sred
    float* sV = smem_u;

    const int m0 = c * CHUNK;
    {
        const float4* src = reinterpret_cast<const float4*>(V + (size_t)m0 * E);
        float4* dst = reinterpret_cast<float4*>(sV);
        for (int i4 = t; i4 < CHUNK * E / 4; i4 += 256) dst[i4] = src[i4];
    }
    __syncthreads();

    u64 acc[4][4];
#pragma unroll
    for (int ii = 0; ii < 4; ++ii)
#pragma unroll
        for (int fp = 0; fp < 4; ++fp) acc[ii][fp] = 0ULL;

    const float* xp = x + ((size_t)b * NN + m0) * F + ig * 4;

    for (int j0 = 0; j0 < 25; j0 += 5) {      // warp rows: w + 8*k, k=0..24
        float4 xa[5];
#pragma unroll
        for (int s = 0; s < 5; ++s)
            xa[s] = *reinterpret_cast<const float4*>(xp + (size_t)(w + 8 * (j0 + s)) * F);
#pragma unroll
        for (int s = 0; s < 5; ++s) {
            const int row = w + 8 * (j0 + s);
            const ulonglong2* vp =
                reinterpret_cast<const ulonglong2*>(sV + row * E + fh * 8);
            ulonglong2 v01 = vp[0];
            ulonglong2 v23 = vp[1];
            u64 a0 = pack2(xa[s].x, xa[s].x);
            u64 a1 = pack2(xa[s].y, xa[s].y);
            u64 a2 = pack2(xa[s].z, xa[s].z);
            u64 a3 = pack2(xa[s].w, xa[s].w);
            acc[0][0] = ffma2(a0, v01.x, acc[0][0]);
            acc[0][1] = ffma2(a0, v01.y, acc[0][1]);
            acc[0][2] = ffma2(a0, v23.x, acc[0][2]);
            acc[0][3] = ffma2(a0, v23.y, acc[0][3]);
            acc[1][0] = ffma2(a1, v01.x, acc[1][0]);
            acc[1][1] = ffma2(a1, v01.y, acc[1][1]);
            acc[1][2] = ffma2(a1, v23.x, acc[1][2]);
            acc[1][3] = ffma2(a1, v23.y, acc[1][3]);
            acc[2][0] = ffma2(a2, v01.x, acc[2][0]);
            acc[2][1] = ffma2(a2, v01.y, acc[2][1]);
            acc[2][2] = ffma2(a2, v23.x, acc[2][2]);
            acc[2][3] = ffma2(a2, v23.y, acc[2][3]);
            acc[3][0] = ffma2(a3, v01.x, acc[3][0]);
            acc[3][1] = ffma2(a3, v01.y, acc[3][1]);
            acc[3][2] = ffma2(a3, v23.x, acc[3][2]);
            acc[3][3] = ffma2(a3, v23.y, acc[3][3]);
        }
    }

    __syncthreads();    // all warps done reading sV; reuse smem_u as sred
#pragma unroll
    for (int ii = 0; ii < 4; ++ii)
#pragma unroll
        for (int fp = 0; fp < 4; ++fp) {
            float2 pr = unpack2(acc[ii][fp]);
            const int i = ig * 4 + ii;
            const int f = fh * 8 + fp * 2;
            *reinterpret_cast<float2*>(&smem_u[(w * 64 + i) * 18 + f]) = pr;
        }
    __syncthreads();

    float* zp = g_zpart + (size_t)(b * NCHUNK + c) * 1024;
#pragma unroll
    for (int r = 0; r < 4; ++r) {
        const int idx = t + r * 256;            // idx = i*16 + f
        const int i = idx >> 4, f = idx & 15;
        float s = 0.f;
#pragma unroll
        for (int ww = 0; ww < 8; ++ww) s += smem_u[(ww * 64 + i) * 18 + f];
        zp[idx] = s;
    }
}

// ---------------------------------------------------------------------------
// Kernel 2a: fold NCHUNK partials -> z.  grid (B, 8), block 128 (256 blocks).
// ---------------------------------------------------------------------------
__global__ void k2a_reduce() {
    const int b   = blockIdx.x;
    const int idx = blockIdx.y * 128 + threadIdx.x;   // 0..1023
    const float* p = g_zpart + (size_t)b * NCHUNK * 1024 + idx;
    float s = 0.f;
#pragma unroll 25
    for (int c = 0; c < NCHUNK; ++c) s += p[(size_t)c * 1024];
    g_z[(size_t)b * 1024 + idx] = s;
}

// ---------------------------------------------------------------------------
// Kernel 2b: w[b,j,e] = sum_{i,f} G[j,i,e,f] * z[b,i,f].
// grid 64 (j), 256 threads; G cached in registers once (read exactly once).
// ---------------------------------------------------------------------------
__global__ void __launch_bounds__(256)
k2b_filter(const float* __restrict__ G) {
    const int j  = blockIdx.x;
    const int t  = threadIdx.x;
    const int i0 = t >> 2, eq = t & 3;
    const int warp = t >> 5, lane = t & 31;

    u64 g2[4][8];     // [e'][f-pair]
    const float* Gp = G + (size_t)((j * 64 + i0) * 16 + eq * 4) * 16;
#pragma unroll
    for (int ep = 0; ep < 4; ++ep)
#pragma unroll
        for (int q = 0; q < 4; ++q) {
            ulonglong2 gq = *reinterpret_cast<const ulonglong2*>(Gp + ep * 16 + q * 4);
            g2[ep][q * 2] = gq.x; g2[ep][q * 2 + 1] = gq.y;
        }

    __shared__ __align__(16) float sw[8][32][16];   // [warp][b][e]  16 KB

    for (int b = 0; b < B; ++b) {
        const float* zp = g_z + (size_t)b * 1024 + i0 * 16;
        u64 z2[8];
#pragma unroll
        for (int q = 0; q < 4; ++q) {
            ulonglong2 zq = *reinterpret_cast<const ulonglong2*>(zp + q * 4);
            z2[q * 2] = zq.x; z2[q * 2 + 1] = zq.y;
        }
        float pv[4];
#pragma unroll
        for (int ep = 0; ep < 4; ++ep) {
            u64 a = 0ULL;
#pragma unroll
            for (int fp = 0; fp < 8; ++fp) a = ffma2(g2[ep][fp], z2[fp], a);
            float2 f = unpack2(a);
            pv[ep] = f.x + f.y;
        }
#pragma unroll
        for (int d = 4; d <= 16; d <<= 1)
#pragma unroll
            for (int ep = 0; ep < 4; ++ep)
                pv[ep] += __shfl_xor_sync(0xffffffffu, pv[ep], d);
        if (lane < 4) {
            float4 q4 = make_float4(pv[0], pv[1], pv[2], pv[3]);
            *reinterpret_cast<float4*>(&sw[warp][b][lane * 4]) = q4;
        }
    }
    __syncthreads();

#pragma unroll
    for (int r = 0; r < 2; ++r) {
        int idx = t + r * 256;                  // 512 outputs = 32b x 16e
        int b = idx >> 4, e = idx & 15;
        float s = 0.f;
#pragma unroll
        for (int w = 0; w < 8; ++w) s += sw[w][b][e];
        g_w[(size_t)(b * JO + j) * E + e] = s;
    }
}

// ---------------------------------------------------------------------------
// Kernel 3: out[b,n,j] = sum_e V[n,e] * w[b,j,e].
// grid (200, 4) = 800 blocks, block 256, occ 4 (32 warps/SM).
// Warp = one b (b = blockIdx.y*8 + warp); lane owns j = 2*lane, 2*lane+1.
// w cache = 16 u64 (32 regs) -> ~50 regs total. V tile in smem, all lanes
// read the same V row per n (broadcast LDS, 1 wavefront). Warp stores 256B
// contiguous per n (float2/lane, streaming __stcs).
// Per-n chain ~61cy for 26 instrs; 32 warps oversubscribe issue -> hidden.
// ---------------------------------------------------------------------------
__global__ void __launch_bounds__(256, 4)
k3_expand(const float* __restrict__ V, float* __restrict__ out) {
    const int t    = threadIdx.x;
    const int w    = t >> 5;
    const int lane = t & 31;
    const int b    = blockIdx.y * 8 + w;
    const int base = blockIdx.x * NPB3;       // 200 tiles x 100 n = 20000 exact

    __shared__ __align__(16) float sv[NPB3 * 16];   // 6.4 KB
    {
        const float4* src = reinterpret_cast<const float4*>(V + (size_t)base * E);
        float4* dst = reinterpret_cast<float4*>(sv);
        for (int i4 = t; i4 < NPB3 * E / 4; i4 += 256) dst[i4] = src[i4];
    }
    __syncthreads();

    u64 w2[2][8];    // [jj][e-pair]
    const float* wp = g_w + (size_t)(b * JO + lane * 2) * E;
#pragma unroll
    for (int jj = 0; jj < 2; ++jj)
#pragma unroll
        for (int q = 0; q < 4; ++q) {
            ulonglong2 wq = *reinterpret_cast<const ulonglong2*>(wp + jj * 16 + q * 4);
            w2[jj][q * 2] = wq.x; w2[jj][q * 2 + 1] = wq.y;
        }

    float* op = out + ((size_t)b * NN + base) * 64 + lane * 2;
    for (int n = 0; n < NPB3; ++n) {
        const ulonglong2* vr = reinterpret_cast<const ulonglong2*>(sv + n * 16);
        u64 a0 = 0ULL, a1 = 0ULL;
#pragma unroll
        for (int q = 0; q < 4; ++q) {
            ulonglong2 vq = vr[q];
            a0 = ffma2(vq.x, w2[0][q * 2],     a0);
            a0 = ffma2(vq.y, w2[0][q * 2 + 1], a0);
            a1 = ffma2(vq.x, w2[1][q * 2],     a1);
            a1 = ffma2(vq.y, w2[1][q * 2 + 1], a1);
        }
        float2 f0 = unpack2(a0), f1 = unpack2(a1);
        float2 r = make_float2(f0.x + f0.y, f1.x + f1.y);
        __stcs(reinterpret_cast<float2*>(op + (size_t)n * 64), r);
    }
}

// ---------------------------------------------------------------------------
extern "C" void kernel_launch(void* const* d_in, const int* in_sizes, int n_in,
                              void* d_out, int out_size) {
    const float* x = nullptr; const float* V = nullptr; const float* G = nullptr;
    for (int i = 0; i < n_in; ++i) {
        if      (in_sizes[i] == B * NN * F)      x = (const float*)d_in[i];
        else if (in_sizes[i] == NN * E)          V = (const float*)d_in[i];
        else if (in_sizes[i] == JO * F * E * E)  G = (const float*)d_in[i];
    }
    float* out = (float*)d_out;

    dim3 g1(NCHUNK, B);
    k1_project<<<g1, 256>>>(x, V);
    dim3 g2a(B, 8);
    k2a_reduce<<<g2a, 128>>>();
    k2b_filter<<<JO, 256>>>(G);
    dim3 g3(NN / NPB3, 4);
    k3_expand<<<g3, 256>>>(V, out);
}

// round 11
// speedup vs baseline: 1.0891x; 1.0891x over previous
#include <cuda_runtime.h>
#include <cstdint>

#define B 32
#define NN 20000
#define F 64
#define JO 64
#define E 16
#define NCHUNK 100
#define CHUNK 200
#define NPB3 136

// Scratch (static device arrays — no allocation)
__device__ float g_zpart[B * NCHUNK * F * E];   // [b][chunk][i*16+f]  13.1 MB
__device__ float g_z[B * F * E];                // [b][i][f]
__device__ float g_w[B * JO * E];               // [b][j][e]

typedef unsigned long long u64;

static __device__ __forceinline__ u64 ffma2(u64 a, u64 b, u64 c) {
    u64 d;
    asm("fma.rn.f32x2 %0, %1, %2, %3;" : "=l"(d) : "l"(a), "l"(b), "l"(c));
    return d;
}
static __device__ __forceinline__ u64 pack2(float lo, float hi) {
    u64 r; asm("mov.b64 %0, {%1, %2};" : "=l"(r) : "f"(lo), "f"(hi)); return r;
}
static __device__ __forceinline__ float2 unpack2(u64 v) {
    float2 f; asm("mov.b64 {%0, %1}, %2;" : "=f"(f.x), "=f"(f.y) : "l"(v)); return f;
}

// ---------------------------------------------------------------------------
// Kernel 1: partial z[b,i,f] = sum_m V[m,f] * x[b,m,i] over one 200-row chunk.
// grid (100, 32) = 3200 blocks, 256 threads, occ 4 (32 warps/SM, was 3).
// smem 36.9KB x 4 = 147.5KB < 228KB; regs ~60 <= 64 (no spill expected).
// Lane: ig = lane>>1 (i quad), fh = lane&1 (f half); 1 LDG.128/warp-row
// (2-way dedup), V staged in smem then broadcast LDS.
// Batch 5 rows -> 5*256B*32w = 40KB/SM x in flight.
// ---------------------------------------------------------------------------
__global__ void __launch_bounds__(256, 4)
k1_project(const float* __restrict__ x, const float* __restrict__ V) {
    const int c    = blockIdx.x;
    const int b    = blockIdx.y;
    const int t    = threadIdx.x;
    const int w    = t >> 5;
    const int lane = t & 31;
    const int ig   = lane >> 1;
    const int fh   = lane & 1;

    __shared__ float smem_u[8 * 64 * 18];     // 36.9 KB: sV (first 3200) then sred
    float* sV = smem_u;

    const int m0 = c * CHUNK;
    {
        const float4* src = reinterpret_cast<const float4*>(V + (size_t)m0 * E);
        float4* dst = reinterpret_cast<float4*>(sV);
        for (int i4 = t; i4 < CHUNK * E / 4; i4 += 256) dst[i4] = src[i4];
    }
    __syncthreads();

    u64 acc[4][4];
#pragma unroll
    for (int ii = 0; ii < 4; ++ii)
#pragma unroll
        for (int fp = 0; fp < 4; ++fp) acc[ii][fp] = 0ULL;

    const float* xp = x + ((size_t)b * NN + m0) * F + ig * 4;

    for (int j0 = 0; j0 < 25; j0 += 5) {      // warp rows: w + 8*k, k=0..24
        float4 xa[5];
#pragma unroll
        for (int s = 0; s < 5; ++s)
            xa[s] = *reinterpret_cast<const float4*>(xp + (size_t)(w + 8 * (j0 + s)) * F);
#pragma unroll
        for (int s = 0; s < 5; ++s) {
            const int row = w + 8 * (j0 + s);
            const ulonglong2* vp =
                reinterpret_cast<const ulonglong2*>(sV + row * E + fh * 8);
            ulonglong2 v01 = vp[0];
            ulonglong2 v23 = vp[1];
            u64 a0 = pack2(xa[s].x, xa[s].x);
            u64 a1 = pack2(xa[s].y, xa[s].y);
            u64 a2 = pack2(xa[s].z, xa[s].z);
            u64 a3 = pack2(xa[s].w, xa[s].w);
            acc[0][0] = ffma2(a0, v01.x, acc[0][0]);
            acc[0][1] = ffma2(a0, v01.y, acc[0][1]);
            acc[0][2] = ffma2(a0, v23.x, acc[0][2]);
            acc[0][3] = ffma2(a0, v23.y, acc[0][3]);
            acc[1][0] = ffma2(a1, v01.x, acc[1][0]);
            acc[1][1] = ffma2(a1, v01.y, acc[1][1]);
            acc[1][2] = ffma2(a1, v23.x, acc[1][2]);
            acc[1][3] = ffma2(a1, v23.y, acc[1][3]);
            acc[2][0] = ffma2(a2, v01.x, acc[2][0]);
            acc[2][1] = ffma2(a2, v01.y, acc[2][1]);
            acc[2][2] = ffma2(a2, v23.x, acc[2][2]);
            acc[2][3] = ffma2(a2, v23.y, acc[2][3]);
            acc[3][0] = ffma2(a3, v01.x, acc[3][0]);
            acc[3][1] = ffma2(a3, v01.y, acc[3][1]);
            acc[3][2] = ffma2(a3, v23.x, acc[3][2]);
            acc[3][3] = ffma2(a3, v23.y, acc[3][3]);
        }
    }

    __syncthreads();    // all warps done reading sV; reuse smem_u as sred
#pragma unroll
    for (int ii = 0; ii < 4; ++ii)
#pragma unroll
        for (int fp = 0; fp < 4; ++fp) {
            float2 pr = unpack2(acc[ii][fp]);
            const int i = ig * 4 + ii;
            const int f = fh * 8 + fp * 2;
            *reinterpret_cast<float2*>(&smem_u[(w * 64 + i) * 18 + f]) = pr;
        }
    __syncthreads();

    float* zp = g_zpart + (size_t)(b * NCHUNK + c) * 1024;
#pragma unroll
    for (int r = 0; r < 4; ++r) {
        const int idx = t + r * 256;            // idx = i*16 + f
        const int i = idx >> 4, f = idx & 15;
        float s = 0.f;
#pragma unroll
        for (int ww = 0; ww < 8; ++ww) s += smem_u[(ww * 64 + i) * 18 + f];
        zp[idx] = s;
    }
}

// ---------------------------------------------------------------------------
// Kernel 2a: fold NCHUNK partials -> z.  grid (B, 8), block 128 (256 blocks).
// ---------------------------------------------------------------------------
__global__ void k2a_reduce() {
    const int b   = blockIdx.x;
    const int idx = blockIdx.y * 128 + threadIdx.x;   // 0..1023
    const float* p = g_zpart + (size_t)b * NCHUNK * 1024 + idx;
    float s = 0.f;
#pragma unroll 25
    for (int c = 0; c < NCHUNK; ++c) s += p[(size_t)c * 1024];
    g_z[(size_t)b * 1024 + idx] = s;
}

// ---------------------------------------------------------------------------
// Kernel 2b: w[b,j,e] = sum_{i,f} G[j,i,e,f] * z[b,i,f].
// grid (64 j, 2 b-halves), 256 threads; each block does 16 b (halved serial
// loop vs R10). G slice cached in registers once (G still read exactly 2x).
// ---------------------------------------------------------------------------
__global__ void __launch_bounds__(256)
k2b_filter(const float* __restrict__ G) {
    const int j  = blockIdx.x;
    const int bH = blockIdx.y;                 // 0/1 -> b in [bH*16, bH*16+16)
    const int t  = threadIdx.x;
    const int i0 = t >> 2, eq = t & 3;
    const int warp = t >> 5, lane = t & 31;

    u64 g2[4][8];     // [e'][f-pair]
    const float* Gp = G + (size_t)((j * 64 + i0) * 16 + eq * 4) * 16;
#pragma unroll
    for (int ep = 0; ep < 4; ++ep)
#pragma unroll
        for (int q = 0; q < 4; ++q) {
            ulonglong2 gq = *reinterpret_cast<const ulonglong2*>(Gp + ep * 16 + q * 4);
            g2[ep][q * 2] = gq.x; g2[ep][q * 2 + 1] = gq.y;
        }

    __shared__ __align__(16) float sw[8][16][16];   // [warp][b_local][e]  8 KB

    for (int bl = 0; bl < 16; ++bl) {
        const int b = bH * 16 + bl;
        const float* zp = g_z + (size_t)b * 1024 + i0 * 16;
        u64 z2[8];
#pragma unroll
        for (int q = 0; q < 4; ++q) {
            ulonglong2 zq = *reinterpret_cast<const ulonglong2*>(zp + q * 4);
            z2[q * 2] = zq.x; z2[q * 2 + 1] = zq.y;
        }
        float pv[4];
#pragma unroll
        for (int ep = 0; ep < 4; ++ep) {
            u64 a = 0ULL;
#pragma unroll
            for (int fp = 0; fp < 8; ++fp) a = ffma2(g2[ep][fp], z2[fp], a);
            float2 f = unpack2(a);
            pv[ep] = f.x + f.y;
        }
#pragma unroll
        for (int d = 4; d <= 16; d <<= 1)
#pragma unroll
            for (int ep = 0; ep < 4; ++ep)
                pv[ep] += __shfl_xor_sync(0xffffffffu, pv[ep], d);
        if (lane < 4) {
            float4 q4 = make_float4(pv[0], pv[1], pv[2], pv[3]);
            *reinterpret_cast<float4*>(&sw[warp][bl][lane * 4]) = q4;
        }
    }
    __syncthreads();

    {
        const int idx = t;                      // 256 outputs = 16b x 16e
        const int bl = idx >> 4, e = idx & 15;
        float s = 0.f;
#pragma unroll
        for (int ww = 0; ww < 8; ++ww) s += sw[ww][bl][e];
        g_w[(size_t)((bH * 16 + bl) * JO + j) * E + e] = s;
    }
}

// ---------------------------------------------------------------------------
// Kernel 3: out[b,n,j] = sum_e V[n,e] * w[b,j,e].
// R5 shape (best measured: lowest warp-instr per output row) + n-unroll x2.
// grid 148 (one wave), block 512: j4 = t&15 (4 j's, STG.128), b = t>>4.
// Warp = 2 b x 16 j-quads; per 2 n: 8 broadcast LDS.128 + 2x32 FFMA2 chains
// (8 independent chains in flight) + 2 STG.128 covering 4 rows.
// STG.128 store-issue floor ~14us vs 18.6 (STG.64) / 24 (STG.32).
// ---------------------------------------------------------------------------
__global__ void __launch_bounds__(512, 1)
k3_expand(const float* __restrict__ V, float* __restrict__ out) {
    const int t    = threadIdx.x;
    const int j4   = t & 15;
    const int b    = t >> 4;
    const int base = blockIdx.x * NPB3;
    const int cnt  = min(NPB3, NN - base);    // 136 or 8 (both even)

    u64 w2[4][8];    // [jj][e-pair]
    const float* wp = g_w + (size_t)(b * JO + j4 * 4) * E;
#pragma unroll
    for (int jj = 0; jj < 4; ++jj)
#pragma unroll
        for (int q = 0; q < 4; ++q) {
            ulonglong2 wq = *reinterpret_cast<const ulonglong2*>(wp + jj * 16 + q * 4);
            w2[jj][q * 2] = wq.x; w2[jj][q * 2 + 1] = wq.y;
        }

    __shared__ __align__(16) float sv[NPB3 * 16];   // 8.7 KB
    for (int idx = t; idx < cnt * 16; idx += 512)
        sv[idx] = V[(size_t)base * 16 + idx];
    __syncthreads();

    float* op = out + ((size_t)b * NN + base) * 64 + j4 * 4;
    for (int n = 0; n < cnt; n += 2) {
        const ulonglong2* vrA = reinterpret_cast<const ulonglong2*>(sv + n * 16);
        const ulonglong2* vrB = reinterpret_cast<const ulonglong2*>(sv + n * 16 + 16);
        u64 a0 = 0ULL, a1 = 0ULL, a2 = 0ULL, a3 = 0ULL;
        u64 c0 = 0ULL, c1 = 0ULL, c2 = 0ULL, c3 = 0ULL;
#pragma unroll
        for (int q = 0; q < 4; ++q) {
            ulonglong2 vq = vrA[q];
            a0 = ffma2(vq.x, w2[0][q * 2],     a0);
            a0 = ffma2(vq.y, w2[0][q * 2 + 1], a0);
            a1 = ffma2(vq.x, w2[1][q * 2],     a1);
            a1 = ffma2(vq.y, w2[1][q * 2 + 1], a1);
            a2 = ffma2(vq.x, w2[2][q * 2],     a2);
            a2 = ffma2(vq.y, w2[2][q * 2 + 1], a2);
            a3 = ffma2(vq.x, w2[3][q * 2],     a3);
            a3 = ffma2(vq.y, w2[3][q * 2 + 1], a3);
            ulonglong2 uq = vrB[q];
            c0 = ffma2(uq.x, w2[0][q * 2],     c0);
            c0 = ffma2(uq.y, w2[0][q * 2 + 1], c0);
            c1 = ffma2(uq.x, w2[1][q * 2],     c1);
            c1 = ffma2(uq.y, w2[1][q * 2 + 1], c1);
            c2 = ffma2(uq.x, w2[2][q * 2],     c2);
            c2 = ffma2(uq.y, w2[2][q * 2 + 1], c2);
            c3 = ffma2(uq.x, w2[3][q * 2],     c3);
            c3 = ffma2(uq.y, w2[3][q * 2 + 1], c3);
        }
        float2 f0 = unpack2(a0), f1 = unpack2(a1), f2 = unpack2(a2), f3 = unpack2(a3);
        float4 rA = make_float4(f0.x + f0.y, f1.x + f1.y, f2.x + f2.y, f3.x + f3.y);
        float2 g0 = unpack2(c0), g1 = unpack2(c1), g2r = unpack2(c2), g3 = unpack2(c3);
        float4 rB = make_float4(g0.x + g0.y, g1.x + g1.y, g2r.x + g2r.y, g3.x + g3.y);
        *reinterpret_cast<float4*>(op + (size_t)n * 64)       = rA;
        *reinterpret_cast<float4*>(op + (size_t)(n + 1) * 64) = rB;
    }
}

// ---------------------------------------------------------------------------
extern "C" void kernel_launch(void* const* d_in, const int* in_sizes, int n_in,
                              void* d_out, int out_size) {
    const float* x = nullptr; const float* V = nullptr; const float* G = nullptr;
    for (int i = 0; i < n_in; ++i) {
        if      (in_sizes[i] == B * NN * F)      x = (const float*)d_in[i];
        else if (in_sizes[i] == NN * E)          V = (const float*)d_in[i];
        else if (in_sizes[i] == JO * F * E * E)  G = (const float*)d_in[i];
    }
    float* out = (float*)d_out;

    dim3 g1(NCHUNK, B);
    k1_project<<<g1, 256>>>(x, V);
    dim3 g2a(B, 8);
    k2a_reduce<<<g2a, 128>>>();
    dim3 g2b(JO, 2);
    k2b_filter<<<g2b, 256>>>(G);
    k3_expand<<<(NN + NPB3 - 1) / NPB3, 512>>>(V, out);
}

// round 12
// speedup vs baseline: 1.3007x; 1.1943x over previous
#include <cuda_runtime.h>
#include <cstdint>

#define B 32
#define NN 20000
#define F 64
#define JO 64
#define E 16
#define NCHUNK 100
#define CHUNK 200
#define NPB3 136

#define XTILE_ROWS 40
#define XTILE_FLOATS (XTILE_ROWS * F)          // 2560 floats = 10240 B
#define XTILE_BYTES (XTILE_FLOATS * 4)

// Scratch (static device arrays — no allocation)
__device__ float g_zpart[B * NCHUNK * F * E];   // 13.1 MB
__device__ float g_z[B * F * E];
__device__ float g_w[B * JO * E];

typedef unsigned long long u64;

static __device__ __forceinline__ u64 ffma2(u64 a, u64 b, u64 c) {
    u64 d;
    asm("fma.rn.f32x2 %0, %1, %2, %3;" : "=l"(d) : "l"(a), "l"(b), "l"(c));
    return d;
}
static __device__ __forceinline__ u64 pack2(float lo, float hi) {
    u64 r; asm("mov.b64 %0, {%1, %2};" : "=l"(r) : "f"(lo), "f"(hi)); return r;
}
static __device__ __forceinline__ float2 unpack2(u64 v) {
    float2 f; asm("mov.b64 {%0, %1}, %2;" : "=f"(f.x), "=f"(f.y) : "l"(v)); return f;
}
static __device__ __forceinline__ void cpa16(uint32_t s, const float* g) {
    asm volatile("cp.async.cg.shared.global [%0], [%1], 16;" :: "r"(s), "l"(g));
}
#define CP_COMMIT() asm volatile("cp.async.commit_group;" ::: "memory")
#define CP_WAIT(n)  asm volatile("cp.async.wait_group %0;" :: "n"(n) : "memory")

// ---------------------------------------------------------------------------
// Kernel 1: partial z[b,i,f] = sum_m V[m,f] * x[b,m,i] over one 200-row chunk.
// grid (100, 32), 256 threads, occ 3.
// cp.async pipeline: x staged in 3 x 10.24KB smem tiles (2-3 groups in
// flight -> ~61 KB/SM outstanding, register-free MLP); V staged via group 0.
// Consumer: warp w owns rows w+8k; lane: ig=lane>>1 (i quad), fh=lane&1
// (f half); 16 FFMA2 per row into 16 f32x2 accumulators (32 regs).
// smem union (43.5 KB): [3 x-stages][V 12.8KB]; reused as sred after loop.
// ---------------------------------------------------------------------------
__global__ void __launch_bounds__(256, 3)
k1_project(const float* __restrict__ x, const float* __restrict__ V) {
    const int c    = blockIdx.x;
    const int b    = blockIdx.y;
    const int t    = threadIdx.x;
    const int w    = t >> 5;
    const int lane = t & 31;
    const int ig   = lane >> 1;
    const int fh   = lane & 1;

    __shared__ __align__(16) float smem_u[10880];   // 43520 B
    float* sV = smem_u + 3 * XTILE_FLOATS;          // 3200 floats (200x16)
    const uint32_t sbase = (uint32_t)__cvta_generic_to_shared(smem_u);

    const int m0 = c * CHUNK;
    const float* xg = x + ((size_t)b * NN + m0) * F;
    const float* Vg = V + (size_t)m0 * E;

    // ---- async producers --------------------------------------------------
    // group 0: V (800 x 16B) + tile 0 ; group k: tile k
    {   // V
        const uint32_t dv = sbase + 3u * XTILE_BYTES;
        cpa16(dv + t * 16,         Vg + t * 4);
        cpa16(dv + (t + 256) * 16, Vg + (t + 256) * 4);
        cpa16(dv + (t + 512) * 16, Vg + (t + 512) * 4);
        if (t < 32) cpa16(dv + (t + 768) * 16, Vg + (t + 768) * 4);
    }
#define ISSUE_TILE(k)                                                        \
    {   const uint32_t dx = sbase + (uint32_t)((k) % 3) * XTILE_BYTES;       \
        const float* src = xg + (size_t)(k) * XTILE_FLOATS;                  \
        cpa16(dx + t * 16,         src + t * 4);                             \
        cpa16(dx + (t + 256) * 16, src + (t + 256) * 4);                     \
        if (t < 128) cpa16(dx + (t + 512) * 16, src + (t + 512) * 4);       \
    }
    ISSUE_TILE(0); CP_COMMIT();
    ISSUE_TILE(1); CP_COMMIT();

    u64 acc[4][4];
#pragma unroll
    for (int ii = 0; ii < 4; ++ii)
#pragma unroll
        for (int fp = 0; fp < 4; ++fp) acc[ii][fp] = 0ULL;

#pragma unroll
    for (int tl = 0; tl < 5; ++tl) {
        if (tl + 2 < 5) { ISSUE_TILE(tl + 2); CP_COMMIT(); }
        if      (tl <  3) CP_WAIT(2);
        else if (tl == 3) CP_WAIT(1);
        else              CP_WAIT(0);
        __syncthreads();

        const float* xb = smem_u + (tl % 3) * XTILE_FLOATS;
#pragma unroll
        for (int k = 0; k < 5; ++k) {
            const int rl = w + 8 * k;                 // local row in tile
            const int rg = tl * XTILE_ROWS + rl;      // row in chunk
            float4 xv = *reinterpret_cast<const float4*>(xb + rl * F + ig * 4);
            const ulonglong2* vp =
                reinterpret_cast<const ulonglong2*>(sV + rg * E + fh * 8);
            ulonglong2 v01 = vp[0];
            ulonglong2 v23 = vp[1];
            u64 a0 = pack2(xv.x, xv.x);
            u64 a1 = pack2(xv.y, xv.y);
            u64 a2 = pack2(xv.z, xv.z);
            u64 a3 = pack2(xv.w, xv.w);
            acc[0][0] = ffma2(a0, v01.x, acc[0][0]);
            acc[0][1] = ffma2(a0, v01.y, acc[0][1]);
            acc[0][2] = ffma2(a0, v23.x, acc[0][2]);
            acc[0][3] = ffma2(a0, v23.y, acc[0][3]);
            acc[1][0] = ffma2(a1, v01.x, acc[1][0]);
            acc[1][1] = ffma2(a1, v01.y, acc[1][1]);
            acc[1][2] = ffma2(a1, v23.x, acc[1][2]);
            acc[1][3] = ffma2(a1, v23.y, acc[1][3]);
            acc[2][0] = ffma2(a2, v01.x, acc[2][0]);
            acc[2][1] = ffma2(a2, v01.y, acc[2][1]);
            acc[2][2] = ffma2(a2, v23.x, acc[2][2]);
            acc[2][3] = ffma2(a2, v23.y, acc[2][3]);
            acc[3][0] = ffma2(a3, v01.x, acc[3][0]);
            acc[3][1] = ffma2(a3, v01.y, acc[3][1]);
            acc[3][2] = ffma2(a3, v23.x, acc[3][2]);
            acc[3][3] = ffma2(a3, v23.y, acc[3][3]);
        }
        __syncthreads();   // all warps done with this buffer before reuse
    }
#undef ISSUE_TILE

    // ---- cross-warp reduction (reuse smem_u as sred[8][64][18]) ----------
#pragma unroll
    for (int ii = 0; ii < 4; ++ii)
#pragma unroll
        for (int fp = 0; fp < 4; ++fp) {
            float2 pr = unpack2(acc[ii][fp]);
            const int i = ig * 4 + ii;
            const int f = fh * 8 + fp * 2;
            *reinterpret_cast<float2*>(&smem_u[(w * 64 + i) * 18 + f]) = pr;
        }
    __syncthreads();

    float* zp = g_zpart + (size_t)(b * NCHUNK + c) * 1024;
#pragma unroll
    for (int r = 0; r < 4; ++r) {
        const int idx = t + r * 256;            // idx = i*16 + f
        const int i = idx >> 4, f = idx & 15;
        float s = 0.f;
#pragma unroll
        for (int ww = 0; ww < 8; ++ww) s += smem_u[(ww * 64 + i) * 18 + f];
        zp[idx] = s;
    }
}

// ---------------------------------------------------------------------------
// Kernel 2a: fold NCHUNK partials -> z.  grid (B, 8), block 128.
// ---------------------------------------------------------------------------
__global__ void k2a_reduce() {
    const int b   = blockIdx.x;
    const int idx = blockIdx.y * 128 + threadIdx.x;
    const float* p = g_zpart + (size_t)b * NCHUNK * 1024 + idx;
    float s = 0.f;
#pragma unroll 25
    for (int c = 0; c < NCHUNK; ++c) s += p[(size_t)c * 1024];
    g_z[(size_t)b * 1024 + idx] = s;
}

// ---------------------------------------------------------------------------
// Kernel 2b: w[b,j,e] = sum_{i,f} G[j,i,e,f] * z[b,i,f].
// grid (64 j, 2 b-halves), 256 threads.
// ---------------------------------------------------------------------------
__global__ void __launch_bounds__(256)
k2b_filter(const float* __restrict__ G) {
    const int j  = blockIdx.x;
    const int bH = blockIdx.y;
    const int t  = threadIdx.x;
    const int i0 = t >> 2, eq = t & 3;
    const int warp = t >> 5, lane = t & 31;

    u64 g2[4][8];
    const float* Gp = G + (size_t)((j * 64 + i0) * 16 + eq * 4) * 16;
#pragma unroll
    for (int ep = 0; ep < 4; ++ep)
#pragma unroll
        for (int q = 0; q < 4; ++q) {
            ulonglong2 gq = *reinterpret_cast<const ulonglong2*>(Gp + ep * 16 + q * 4);
            g2[ep][q * 2] = gq.x; g2[ep][q * 2 + 1] = gq.y;
        }

    __shared__ __align__(16) float sw[8][16][16];

    for (int bl = 0; bl < 16; ++bl) {
        const int b = bH * 16 + bl;
        const float* zp = g_z + (size_t)b * 1024 + i0 * 16;
        u64 z2[8];
#pragma unroll
        for (int q = 0; q < 4; ++q) {
            ulonglong2 zq = *reinterpret_cast<const ulonglong2*>(zp + q * 4);
            z2[q * 2] = zq.x; z2[q * 2 + 1] = zq.y;
        }
        float pv[4];
#pragma unroll
        for (int ep = 0; ep < 4; ++ep) {
            u64 a = 0ULL;
#pragma unroll
            for (int fp = 0; fp < 8; ++fp) a = ffma2(g2[ep][fp], z2[fp], a);
            float2 f = unpack2(a);
            pv[ep] = f.x + f.y;
        }
#pragma unroll
        for (int d = 4; d <= 16; d <<= 1)
#pragma unroll
            for (int ep = 0; ep < 4; ++ep)
                pv[ep] += __shfl_xor_sync(0xffffffffu, pv[ep], d);
        if (lane < 4) {
            float4 q4 = make_float4(pv[0], pv[1], pv[2], pv[3]);
            *reinterpret_cast<float4*>(&sw[warp][bl][lane * 4]) = q4;
        }
    }
    __syncthreads();

    {
        const int bl = t >> 4, e = t & 15;
        float s = 0.f;
#pragma unroll
        for (int ww = 0; ww < 8; ++ww) s += sw[ww][bl][e];
        g_w[(size_t)((bH * 16 + bl) * JO + j) * E + e] = s;
    }
}

// ---------------------------------------------------------------------------
// Kernel 3: out[b,n,j] = sum_e V[n,e] * w[b,j,e].  (R11 shape, unchanged)
// ---------------------------------------------------------------------------
__global__ void __launch_bounds__(512, 1)
k3_expand(const float* __restrict__ V, float* __restrict__ out) {
    const int t    = threadIdx.x;
    const int j4   = t & 15;
    const int b    = t >> 4;
    const int base = blockIdx.x * NPB3;
    const int cnt  = min(NPB3, NN - base);

    u64 w2[4][8];
    const float* wp = g_w + (size_t)(b * JO + j4 * 4) * E;
#pragma unroll
    for (int jj = 0; jj < 4; ++jj)
#pragma unroll
        for (int q = 0; q < 4; ++q) {
            ulonglong2 wq = *reinterpret_cast<const ulonglong2*>(wp + jj * 16 + q * 4);
            w2[jj][q * 2] = wq.x; w2[jj][q * 2 + 1] = wq.y;
        }

    __shared__ __align__(16) float sv[NPB3 * 16];
    for (int idx = t; idx < cnt * 16; idx += 512)
        sv[idx] = V[(size_t)base * 16 + idx];
    __syncthreads();

    float* op = out + ((size_t)b * NN + base) * 64 + j4 * 4;
    for (int n = 0; n < cnt; n += 2) {
        const ulonglong2* vrA = reinterpret_cast<const ulonglong2*>(sv + n * 16);
        const ulonglong2* vrB = reinterpret_cast<const ulonglong2*>(sv + n * 16 + 16);
        u64 a0 = 0ULL, a1 = 0ULL, a2 = 0ULL, a3 = 0ULL;
        u64 c0 = 0ULL, c1 = 0ULL, c2 = 0ULL, c3 = 0ULL;
#pragma unroll
        for (int q = 0; q < 4; ++q) {
            ulonglong2 vq = vrA[q];
            a0 = ffma2(vq.x, w2[0][q * 2],     a0);
            a0 = ffma2(vq.y, w2[0][q * 2 + 1], a0);
            a1 = ffma2(vq.x, w2[1][q * 2],     a1);
            a1 = ffma2(vq.y, w2[1][q * 2 + 1], a1);
            a2 = ffma2(vq.x, w2[2][q * 2],     a2);
            a2 = ffma2(vq.y, w2[2][q * 2 + 1], a2);
            a3 = ffma2(vq.x, w2[3][q * 2],     a3);
            a3 = ffma2(vq.y, w2[3][q * 2 + 1], a3);
            ulonglong2 uq = vrB[q];
            c0 = ffma2(uq.x, w2[0][q * 2],     c0);
            c0 = ffma2(uq.y, w2[0][q * 2 + 1], c0);
            c1 = ffma2(uq.x, w2[1][q * 2],     c1);
            c1 = ffma2(uq.y, w2[1][q * 2 + 1], c1);
            c2 = ffma2(uq.x, w2[2][q * 2],     c2);
            c2 = ffma2(uq.y, w2[2][q * 2 + 1], c2);
            c3 = ffma2(uq.x, w2[3][q * 2],     c3);
            c3 = ffma2(uq.y, w2[3][q * 2 + 1], c3);
        }
        float2 f0 = unpack2(a0), f1 = unpack2(a1), f2 = unpack2(a2), f3 = unpack2(a3);
        float4 rA = make_float4(f0.x + f0.y, f1.x + f1.y, f2.x + f2.y, f3.x + f3.y);
        float2 g0 = unpack2(c0), g1 = unpack2(c1), g2r = unpack2(c2), g3 = unpack2(c3);
        float4 rB = make_float4(g0.x + g0.y, g1.x + g1.y, g2r.x + g2r.y, g3.x + g3.y);
        *reinterpret_cast<float4*>(op + (size_t)n * 64)       = rA;
        *reinterpret_cast<float4*>(op + (size_t)(n + 1) * 64) = rB;
    }
}

// ---------------------------------------------------------------------------
extern "C" void kernel_launch(void* const* d_in, const int* in_sizes, int n_in,
                              void* d_out, int out_size) {
    const float* x = nullptr; const float* V = nullptr; const float* G = nullptr;
    for (int i = 0; i < n_in; ++i) {
        if      (in_sizes[i] == B * NN * F)      x = (const float*)d_in[i];
        else if (in_sizes[i] == NN * E)          V = (const float*)d_in[i];
        else if (in_sizes[i] == JO * F * E * E)  G = (const float*)d_in[i];
    }
    float* out = (float*)d_out;

    dim3 g1(NCHUNK, B);
    k1_project<<<g1, 256>>>(x, V);
    dim3 g2a(B, 8);
    k2a_reduce<<<g2a, 128>>>();
    dim3 g2b(JO, 2);
    k2b_filter<<<g2b, 256>>>(G);
    k3_expand<<<(NN + NPB3 - 1) / NPB3, 512>>>(V, out);
}